// round 15
// baseline (speedup 1.0000x reference)
#include <cuda_runtime.h>
#include <cuda_fp16.h>
#include <cstdint>

#define B    32
#define NN   2000
#define TD   384
#define E    64
#define TT   24
#define DD   16

#define BR   64
#define NTK  32                          // 32 tiles x 64 kv (padded to 2048)

// ---- K/V gmem tile-image geometry (exact smem images, 72-half rows)
#define KIMG_TILE_H   4608               // 64 rows x 72 halves
#define KIMG_TILE_B   9216
#define KIMG_BATCH_H  147456             // 32 tiles
#define VIMG_TILE_H   27648              // 384 rows x 72 halves
#define VIMG_TILE_B   55296

// ---- attn smem byte layout
#define OFF_Q   0                        // 64 rows x 144B = 9216
#define OFF_MB  9216                     // 2 mbarriers
#define OFF_ST  9728                     // 2 stages x (K 9216 + V 55296)
#define STG     64512
#define SMEM_ATT (OFF_ST + 2*STG)        // 138752

// ---- k1 tensor-GEMM layout
#define K1M     128
#define K1_XST  68
#define K1_XTILE 34816
#define K1_OFF_X 0
#define K1_OFF_W 69632
#define K1_OFF_C 174080
#define K1_SMEM  175616

#define SCALE_S 0.022360679774997897f    // 1/sqrt(2000)

typedef unsigned long long u64;

__device__ __align__(16) __half g_qf[B*NN*E];        // pre-scaled by SCALE_S
__device__ __align__(16) __half g_kimg[B*KIMG_BATCH_H];
__device__ __align__(16) __half g_vimg[NTK*VIMG_TILE_H];
__device__ __align__(16) __half g_xh[B*NN*TD];
__device__ __align__(16) __half g_wt[3*128*136];

// =================== helpers ===================
__device__ __forceinline__ uint32_t cvta_s(const void* p){
    return (uint32_t)__cvta_generic_to_shared(p);
}
__device__ __forceinline__ void cpa16(uint32_t d, const void* s){
    asm volatile("cp.async.cg.shared.global [%0],[%1],16;" :: "r"(d), "l"(s));
}
#define CP_COMMIT() asm volatile("cp.async.commit_group;")

__device__ __forceinline__ void mma16816h(float* d, const uint32_t* a, const uint32_t* b){
    asm volatile("mma.sync.aligned.m16n8k16.row.col.f32.f16.f16.f32 "
        "{%0,%1,%2,%3},{%4,%5,%6,%7},{%8,%9},{%0,%1,%2,%3};"
        : "+f"(d[0]), "+f"(d[1]), "+f"(d[2]), "+f"(d[3])
        : "r"(a[0]), "r"(a[1]), "r"(a[2]), "r"(a[3]), "r"(b[0]), "r"(b[1]));
}

__device__ __forceinline__ int imin(int a, int b){ return a < b ? a : b; }
__device__ __forceinline__ uint32_t pkhf(float a, float b){
    __half2 h = __floats2half2_rn(a, b);
    return *(uint32_t*)&h;
}

__device__ __forceinline__ void mbar_init(uint32_t a, uint32_t cnt){
    asm volatile("mbarrier.init.shared.b64 [%0], %1;" :: "r"(a), "r"(cnt) : "memory");
}
__device__ __forceinline__ void mbar_wait(uint32_t a, uint32_t parity){
    uint32_t done;
    asm volatile("{.reg .pred p; mbarrier.try_wait.parity.acquire.cta.shared::cta.b64 p, [%1], %2; selp.b32 %0,1,0,p;}"
        : "=r"(done) : "r"(a), "r"(parity) : "memory");
    if (!done)
        asm volatile("{.reg .pred P1; WL%=: mbarrier.try_wait.parity.acquire.cta.shared::cta.b64 P1, [%0], %1, 0x989680;"
                     "@P1 bra.uni WD%=; bra.uni WL%=; WD%=: }" :: "r"(a), "r"(parity) : "memory");
}

// ============================================================
// prep kernels
// ============================================================
__global__ __launch_bounds__(256) void prep_vt(const float* __restrict__ normal){
    int idx = blockIdx.x*256 + threadIdx.x;      // 32*384*64 = 786432
    if (idx < NTK*384*64){
        int t = idx / (384*64);
        int rem = idx - t*(384*64);
        int n = rem >> 6, j = rem & 63;
        int kv = t*64 + j;
        float v = (kv < NN) ? normal[(size_t)kv*TD + n] : 0.f;
        g_vimg[(size_t)t*VIMG_TILE_H + n*72 + j] = __float2half_rn(v);
    }
}

__global__ __launch_bounds__(256) void prep_x(const float* __restrict__ x){
    int idx = blockIdx.x*256 + threadIdx.x;
    if (idx < (B*NN*TD)/4){
        float4 v = ((const float4*)x)[idx];
        uint2 o;
        o.x = pkhf(v.x, v.y);
        o.y = pkhf(v.z, v.w);
        ((uint2*)g_xh)[idx] = o;
    }
}

__global__ __launch_bounds__(256) void prep_wt(const float* __restrict__ Wq,
                                               const float* __restrict__ Wk){
    int idx = blockIdx.x*256 + threadIdx.x;
    if (idx < 3*128*136){
        int c = idx / (128*136);
        int rem = idx - c*(128*136);
        int n = rem / 136, kk = rem - n*136;
        float v = 0.f;
        if (kk < 128){
            int k = c*128 + kk;
            v = (n < 64) ? Wq[k*64 + n] : Wk[k*64 + (n - 64)];
        }
        g_wt[idx] = __float2half_rn(v);
    }
}

// ============================================================
// Kernel 1: y = xh @ W (fp16 HMMA), +bias, LN -> g_qf (pre-scaled) / g_kimg
// ============================================================
__device__ __forceinline__ void k1_prefx(char* sm, int tid, long base, int c, int s){
#pragma unroll
    for (int j = 0; j < 8; j++){
        int idx = tid + j*256;
        int row = idx >> 4, ch = idx & 15;
        const __half* src = g_xh + (base + row)*(size_t)TD + c*128 + ch*8;
        cpa16(cvta_s(sm + K1_OFF_X + s*K1_XTILE + row*272 + ch*16), src);
    }
    CP_COMMIT();
}

__global__ __launch_bounds__(256, 1) void k1_tc(
    const float* __restrict__ bq, const float* __restrict__ bk,
    const float* __restrict__ g0, const float* __restrict__ beta0,
    const float* __restrict__ g1, const float* __restrict__ beta1)
{
    extern __shared__ char sm[];
    const int tid = threadIdx.x;
    const int wid = tid >> 5, lane = tid & 31;
    const int gid = lane >> 2, tig = lane & 3;
    const int r0 = wid * 16;
    const long base = (long)blockIdx.x * K1M;

    float* cs = (float*)(sm + K1_OFF_C);
    if (tid < 128){
        cs[tid]       = (tid < 64) ? bq[tid] : bk[tid - 64];
        cs[128 + tid] = (tid < 64) ? g0[tid] : g1[tid - 64];
        cs[256 + tid] = (tid < 64) ? beta0[tid] : beta1[tid - 64];
    }

    k1_prefx(sm, tid, base, 0, 0);
    {
#pragma unroll
        for (int j = 0; j < 26; j++){
            int i = tid + j*256;
            if (i < 6528)
                cpa16(cvta_s(sm + K1_OFF_W + i*16), (const char*)g_wt + i*16);
        }
        CP_COMMIT();
    }
    k1_prefx(sm, tid, base, 1, 1);

    float acc[16][4];
#pragma unroll
    for (int nt = 0; nt < 16; nt++)
#pragma unroll
        for (int j = 0; j < 4; j++) acc[nt][j] = 0.f;

#pragma unroll
    for (int c = 0; c < 3; c++){
        if (c < 2) asm volatile("cp.async.wait_group 1;");
        else       asm volatile("cp.async.wait_group 0;");
        __syncthreads();
        const uint32_t* xs  = (const uint32_t*)(sm + K1_OFF_X + (c & 1)*K1_XTILE);
        const uint32_t* wsp = (const uint32_t*)(sm + K1_OFF_W + c*K1_XTILE);
#pragma unroll
        for (int ks = 0; ks < 8; ks++){
            int qa = (r0 + gid)*K1_XST + ks*8 + tig;
            int qb = qa + 8*K1_XST;
            uint32_t a[4] = { xs[qa], xs[qb], xs[qa+4], xs[qb+4] };
#pragma unroll
            for (int nt = 0; nt < 16; nt++){
                int kb = (nt*8 + gid)*K1_XST + ks*8 + tig;
                uint32_t bfr[2] = { wsp[kb], wsp[kb+4] };
                mma16816h(acc[nt], a, bfr);
            }
        }
        __syncthreads();
        if (c == 0){ k1_prefx(sm, tid, base, 2, 0); }
    }

    const int c0 = tig*2;
#pragma unroll
    for (int nt = 0; nt < 16; nt++){
        int col = (nt < 8) ? nt*8 + c0 : 64 + (nt - 8)*8 + c0;
        float b0 = cs[col], b1 = cs[col + 1];
        acc[nt][0] += b0; acc[nt][1] += b1;
        acc[nt][2] += b0; acc[nt][3] += b1;
    }
    float sqA=0,ssA=0,skA=0,sskA=0, sqB=0,ssB=0,skB=0,sskB=0;
#pragma unroll
    for (int nt = 0; nt < 8; nt++){
        sqA += acc[nt][0] + acc[nt][1];
        ssA += acc[nt][0]*acc[nt][0] + acc[nt][1]*acc[nt][1];
        sqB += acc[nt][2] + acc[nt][3];
        ssB += acc[nt][2]*acc[nt][2] + acc[nt][3]*acc[nt][3];
    }
#pragma unroll
    for (int nt = 8; nt < 16; nt++){
        skA += acc[nt][0] + acc[nt][1];
        sskA += acc[nt][0]*acc[nt][0] + acc[nt][1]*acc[nt][1];
        skB += acc[nt][2] + acc[nt][3];
        sskB += acc[nt][2]*acc[nt][2] + acc[nt][3]*acc[nt][3];
    }
#pragma unroll
    for (int off = 1; off <= 2; off <<= 1){
        sqA += __shfl_xor_sync(0xffffffffu, sqA, off);
        ssA += __shfl_xor_sync(0xffffffffu, ssA, off);
        skA += __shfl_xor_sync(0xffffffffu, skA, off);
        sskA += __shfl_xor_sync(0xffffffffu, sskA, off);
        sqB += __shfl_xor_sync(0xffffffffu, sqB, off);
        ssB += __shfl_xor_sync(0xffffffffu, ssB, off);
        skB += __shfl_xor_sync(0xffffffffu, skB, off);
        sskB += __shfl_xor_sync(0xffffffffu, sskB, off);
    }
    const float inv64 = 1.f/64.f;
    float muqA = sqA*inv64, rsqA = rsqrtf(ssA*inv64 - muqA*muqA + 1e-5f) * SCALE_S;
    float muqB = sqB*inv64, rsqB = rsqrtf(ssB*inv64 - muqB*muqB + 1e-5f) * SCALE_S;
    float mukA = skA*inv64, rskA = rsqrtf(sskA*inv64 - mukA*mukA + 1e-5f);
    float mukB = skB*inv64, rskB = rsqrtf(sskB*inv64 - mukB*mukB + 1e-5f);

    const int grA = (int)(base + r0 + gid);
    const int grB = grA + 8;
    const int bA = grA / NN, nAq = grA - bA*NN;
    const int bB = grB / NN, nBq = grB - bB*NN;
    __half* kdstA = g_kimg + (size_t)bA*KIMG_BATCH_H + (nAq >> 6)*KIMG_TILE_H + (nAq & 63)*72;
    __half* kdstB = g_kimg + (size_t)bB*KIMG_BATCH_H + (nBq >> 6)*KIMG_TILE_H + (nBq & 63)*72;

#pragma unroll
    for (int nt = 0; nt < 8; nt++){
        int col = nt*8 + c0;
        float ga = cs[128 + col], gb = cs[128 + col + 1];
        float ba = cs[256 + col] * SCALE_S, bb = cs[256 + col + 1] * SCALE_S;
        *(uint32_t*)(g_qf + (size_t)grA*E + col) =
            pkhf((acc[nt][0]-muqA)*rsqA*ga + ba, (acc[nt][1]-muqA)*rsqA*gb + bb);
        *(uint32_t*)(g_qf + (size_t)grB*E + col) =
            pkhf((acc[nt][2]-muqB)*rsqB*ga + ba, (acc[nt][3]-muqB)*rsqB*gb + bb);
    }
#pragma unroll
    for (int nt = 8; nt < 16; nt++){
        int col = (nt - 8)*8 + c0;
        float ga = cs[128 + 64 + col], gb = cs[128 + 64 + col + 1];
        float ba = cs[256 + 64 + col], bb = cs[256 + 64 + col + 1];
        *(uint32_t*)(kdstA + col) =
            pkhf((acc[nt][0]-mukA)*rskA*ga + ba, (acc[nt][1]-mukA)*rskA*gb + bb);
        *(uint32_t*)(kdstB + col) =
            pkhf((acc[nt][2]-mukB)*rskB*ga + ba, (acc[nt][3]-mukB)*rskB*gb + bb);
    }
}

// ============================================================
// Kernel 2: fp16 mma.sync flash attention.
// BR=64, 128 threads = 4 warps x 16 rows; 64-kv bulk double-buffered
// stages; P in registers; __expf; scale pre-folded into q.
// ============================================================
__device__ __forceinline__ void issue_tile(char* smem, int t, int b){
    if (t < NTK){
        int st = t & 1;
        uint32_t mbar = cvta_s(smem + OFF_MB + st*8);
        uint32_t kdst = cvta_s(smem + OFF_ST + st*STG);
        uint32_t vdst = kdst + KIMG_TILE_B;
        asm volatile("mbarrier.arrive.expect_tx.shared.b64 _, [%0], %1;"
            :: "r"(mbar), "r"((uint32_t)STG) : "memory");
        const char* ksrc = (const char*)(g_kimg + (size_t)b*KIMG_BATCH_H) + (size_t)t*KIMG_TILE_B;
        const char* vsrc = (const char*)g_vimg + (size_t)t*VIMG_TILE_B;
        asm volatile("cp.async.bulk.shared::cta.global.mbarrier::complete_tx::bytes [%0], [%1], %2, [%3];"
            :: "r"(kdst), "l"(ksrc), "r"((uint32_t)KIMG_TILE_B), "r"(mbar) : "memory");
        asm volatile("cp.async.bulk.shared::cta.global.mbarrier::complete_tx::bytes [%0], [%1], %2, [%3];"
            :: "r"(vdst), "l"(vsrc), "r"((uint32_t)VIMG_TILE_B), "r"(mbar) : "memory");
    }
}

__global__ __launch_bounds__(128, 1) void attn_mma(
    const float* __restrict__ x,
    const float* __restrict__ Win,
    float* __restrict__ out)
{
    extern __shared__ char smem[];
    const int tid = threadIdx.x;
    const int wid = tid >> 5, lane = tid & 31;
    const int gid = lane >> 2, tig = lane & 3;
    const int b = blockIdx.y;
    const int n0 = blockIdx.x * BR;
    const int r0 = wid * 16;

    // Q prologue: 64 rows x 8 chunks = 512 chunks
#pragma unroll
    for (int j = 0; j < 4; j++){
        int c = tid + j*128;
        int row = c >> 3, ch = c & 7;
        int g = imin(n0 + row, NN-1);
        const __half* src = g_qf + ((size_t)b*NN + g)*E + ch*8;
        cpa16(cvta_s(smem + OFF_Q + row*144 + ch*16), src);
    }
    CP_COMMIT();

    if (tid == 0){
        mbar_init(cvta_s(smem + OFF_MB), 1);
        mbar_init(cvta_s(smem + OFF_MB + 8), 1);
    }
    __syncthreads();
    if (tid == 0){
        issue_tile(smem, 0, b);
        issue_tile(smem, 1, b);
    }
    asm volatile("cp.async.wait_group 0;");
    __syncthreads();

    float dacc[48][4];
#pragma unroll
    for (int nt = 0; nt < 48; nt++)
#pragma unroll
        for (int c = 0; c < 4; c++) dacc[nt][c] = 0.f;
    float lA = 0.f, lB = 0.f;

    const uint32_t* qf_s = (const uint32_t*)(smem + OFF_Q);

    for (int t = 0; t < NTK; t++){
        const int st = t & 1;
        mbar_wait(cvta_s(smem + OFF_MB + st*8), (t >> 1) & 1);

        const uint32_t* kh = (const uint32_t*)(smem + OFF_ST + st*STG);
        const uint32_t* vh = (const uint32_t*)(smem + OFF_ST + st*STG + KIMG_TILE_B);

#pragma unroll
        for (int sub = 0; sub < 2; sub++){
            // ---- S = Q.K (16 MMAs/warp); q pre-scaled
            float sacc[4][4];
#pragma unroll
            for (int nt = 0; nt < 4; nt++)
#pragma unroll
                for (int c = 0; c < 4; c++) sacc[nt][c] = 0.f;
#pragma unroll
            for (int ks = 0; ks < 4; ks++){
                int qa = (r0 + gid)*36 + ks*8 + tig;
                int qb = qa + 8*36;
                uint32_t ah[4] = { qf_s[qa], qf_s[qb], qf_s[qa+4], qf_s[qb+4] };
#pragma unroll
                for (int nt = 0; nt < 4; nt++){
                    int kb = (sub*32 + nt*8 + gid)*36 + ks*8 + tig;
                    uint32_t bh[2] = { kh[kb], kh[kb+4] };
                    mma16816h(sacc[nt], ah, bh);
                }
            }

            // ---- exp (MUFU), masked
#pragma unroll
            for (int nt = 0; nt < 4; nt++){
                int colg = t*64 + sub*32 + nt*8 + tig*2;
                bool m0 = colg < NN, m1 = (colg + 1) < NN;
                float p0 = m0 ? __expf(sacc[nt][0]) : 0.f;
                float p1 = m1 ? __expf(sacc[nt][1]) : 0.f;
                float p2 = m0 ? __expf(sacc[nt][2]) : 0.f;
                float p3 = m1 ? __expf(sacc[nt][3]) : 0.f;
                lA += p0 + p1; lB += p2 + p3;
                sacc[nt][0] = p0; sacc[nt][1] = p1;
                sacc[nt][2] = p2; sacc[nt][3] = p3;
            }

            // ---- PV: P a-frags from sacc
#pragma unroll
            for (int ks = 0; ks < 2; ks++){
                uint32_t pa[4] = {
                    pkhf(sacc[2*ks][0],   sacc[2*ks][1]),
                    pkhf(sacc[2*ks][2],   sacc[2*ks][3]),
                    pkhf(sacc[2*ks+1][0], sacc[2*ks+1][1]),
                    pkhf(sacc[2*ks+1][2], sacc[2*ks+1][3])
                };
#pragma unroll
                for (int nt = 0; nt < 48; nt++){
                    int vb = (nt*8 + gid)*36 + sub*16 + ks*8 + tig;
                    uint32_t bh[2] = { vh[vb], vh[vb+4] };
                    mma16816h(dacc[nt], pa, bh);
                }
            }
        }
        __syncthreads();                 // all warps done with stage st
        if (tid == 0) issue_tile(smem, t + 2, b);
    }

    // ---- epilogue
    lA += __shfl_xor_sync(0xffffffffu, lA, 1);
    lA += __shfl_xor_sync(0xffffffffu, lA, 2);
    lB += __shfl_xor_sync(0xffffffffu, lB, 1);
    lB += __shfl_xor_sync(0xffffffffu, lB, 2);
    const float invA = 1.f / lA;
    const float invB = 1.f / lB;

    const int nA = imin(n0 + r0 + gid, NN-1);
    const int nB = imin(n0 + r0 + gid + 8, NN-1);
    float q16A[DD], q16B[DD];
    {
        const float* xa = x + ((size_t)b*NN + nA)*TD + (TT-1)*DD;
        const float* xb = x + ((size_t)b*NN + nB)*TD + (TT-1)*DD;
#pragma unroll
        for (int dp = 0; dp < DD; dp++){
            float sa = 0.f, sb = 0.f;
#pragma unroll
            for (int d = 0; d < DD; d++){
                float w = Win[d*DD + dp];
                sa = fmaf(xa[d], w, sa);
                sb = fmaf(xb[d], w, sb);
            }
            q16A[dp] = sa; q16B[dp] = sb;
        }
    }

    float wAr[TT], wBr[TT];
#pragma unroll
    for (int t2 = 0; t2 < TT; t2++){
        int nt0 = 2*t2, nt1 = nt0 + 1;
        float aA = q16A[tig*2]   * dacc[nt0][0] + q16A[tig*2+1]   * dacc[nt0][1]
                 + q16A[8+tig*2] * dacc[nt1][0] + q16A[9+tig*2]   * dacc[nt1][1];
        float aB = q16B[tig*2]   * dacc[nt0][2] + q16B[tig*2+1]   * dacc[nt0][3]
                 + q16B[8+tig*2] * dacc[nt1][2] + q16B[9+tig*2]   * dacc[nt1][3];
        aA += __shfl_xor_sync(0xffffffffu, aA, 1);
        aA += __shfl_xor_sync(0xffffffffu, aA, 2);
        aB += __shfl_xor_sync(0xffffffffu, aB, 1);
        aB += __shfl_xor_sync(0xffffffffu, aB, 2);
        wAr[t2] = aA * invA;
        wBr[t2] = aB * invB;
    }
    {
        float mA = -1e30f, mB = -1e30f;
#pragma unroll
        for (int t2 = 0; t2 < TT; t2++){ mA = fmaxf(mA, wAr[t2]); mB = fmaxf(mB, wBr[t2]); }
        float sA = 0.f, sB = 0.f;
#pragma unroll
        for (int t2 = 0; t2 < TT; t2++){
            float eA = __expf(wAr[t2] - mA); wAr[t2] = eA; sA += eA;
            float eB = __expf(wBr[t2] - mB); wBr[t2] = eB; sB += eB;
        }
        float iA = 1.f / sA, iB = 1.f / sB;
#pragma unroll
        for (int t2 = 0; t2 < TT; t2++){ wAr[t2] *= iA; wBr[t2] *= iB; }
    }

    const bool vA = (n0 + r0 + gid) < NN;
    const bool vB = (n0 + r0 + gid + 8) < NN;
    float* orowA = out + ((size_t)b*NN + nA)*TD;
    float* orowB = out + ((size_t)b*NN + nB)*TD;
#pragma unroll
    for (int nt = 0; nt < 48; nt++){
        int col = nt*8 + tig*2;
        int t2 = nt >> 1;
        if (vA){
            float2 v; v.x = fmaf(dacc[nt][0], invA, wAr[t2]);
            v.y = fmaf(dacc[nt][1], invA, wAr[t2]);
            *(float2*)(orowA + col) = v;
        }
        if (vB){
            float2 v; v.x = fmaf(dacc[nt][2], invB, wBr[t2]);
            v.y = fmaf(dacc[nt][3], invB, wBr[t2]);
            *(float2*)(orowB + col) = v;
        }
    }
}

// ============================================================
extern "C" void kernel_launch(void* const* d_in, const int* in_sizes, int n_in,
                              void* d_out, int out_size)
{
    (void)in_sizes; (void)n_in; (void)out_size;
    const float* x     = (const float*)d_in[0];
    const float* Wq    = (const float*)d_in[1];
    const float* bq    = (const float*)d_in[2];
    const float* Wk    = (const float*)d_in[3];
    const float* bk    = (const float*)d_in[4];
    const float* g0    = (const float*)d_in[5];
    const float* beta0 = (const float*)d_in[6];
    const float* g1    = (const float*)d_in[7];
    const float* beta1 = (const float*)d_in[8];
    const float* nrm   = (const float*)d_in[9];
    const float* Win   = (const float*)d_in[10];
    float* out = (float*)d_out;

    cudaFuncSetAttribute(k1_tc,    cudaFuncAttributeMaxDynamicSharedMemorySize, K1_SMEM);
    cudaFuncSetAttribute(attn_mma, cudaFuncAttributeMaxDynamicSharedMemorySize, SMEM_ATT);

    prep_vt<<<(NTK*384*64 + 255)/256, 256>>>(nrm);
    prep_x<<<((B*NN*TD)/4 + 255)/256, 256>>>(x);
    prep_wt<<<(3*128*136 + 255)/256, 256>>>(Wq, Wk);

    k1_tc<<<(B*NN)/K1M, 256, K1_SMEM>>>(bq, bk, g0, beta0, g1, beta1);

    dim3 grid((NN + BR - 1)/BR, B);
    attn_mma<<<grid, 128, SMEM_ATT>>>(x, Win, out);
}

// round 16
// speedup vs baseline: 1.1244x; 1.1244x over previous
#include <cuda_runtime.h>
#include <cuda_fp16.h>
#include <cstdint>

#define B    32
#define NN   2000
#define TD   384
#define E    64
#define TT   24
#define DD   16

#define BR   64
#define NTK  63                          // 63 tiles x 32 kv

// ---- K/V gmem tile-image geometry (exact smem images)
#define KIMG_TILE_H   2304               // 32 rows x 72 halves
#define KIMG_TILE_B   4608
#define KIMG_BATCH_H  145152             // 63 tiles
#define VIMG_TILE_H   15360              // 384 rows x 40 halves
#define VIMG_TILE_B   30720

// ---- attn smem byte layout
#define OFF_Q   0                        // 64 rows x 144B = 9216
#define OFF_MB  9216                     // 2 mbarriers
#define OFF_ST  9728                     // 2 stages x (K 4608 + V 30720)
#define STG     35328
#define SMEM_ATT (OFF_ST + 2*STG)        // 80384

// ---- k1 tensor-GEMM layout
#define K1M     128
#define K1_XST  68
#define K1_XTILE 34816
#define K1_OFF_X 0
#define K1_OFF_W 69632
#define K1_OFF_C 174080
#define K1_SMEM  175616

#define SCALE_S 0.022360679774997897f    // 1/sqrt(2000)

typedef unsigned long long u64;

__device__ __align__(16) __half g_qf[B*NN*E];        // pre-scaled by SCALE_S
__device__ __align__(16) __half g_kimg[B*KIMG_BATCH_H];
__device__ __align__(16) __half g_vimg[NTK*VIMG_TILE_H];
__device__ __align__(16) __half g_xh[B*NN*TD];
__device__ __align__(16) __half g_wt[3*128*136];

// =================== helpers ===================
__device__ __forceinline__ uint32_t cvta_s(const void* p){
    return (uint32_t)__cvta_generic_to_shared(p);
}
__device__ __forceinline__ void cpa16(uint32_t d, const void* s){
    asm volatile("cp.async.cg.shared.global [%0],[%1],16;" :: "r"(d), "l"(s));
}
#define CP_COMMIT() asm volatile("cp.async.commit_group;")

__device__ __forceinline__ void mma16816h(float* d, const uint32_t* a, const uint32_t* b){
    asm volatile("mma.sync.aligned.m16n8k16.row.col.f32.f16.f16.f32 "
        "{%0,%1,%2,%3},{%4,%5,%6,%7},{%8,%9},{%0,%1,%2,%3};"
        : "+f"(d[0]), "+f"(d[1]), "+f"(d[2]), "+f"(d[3])
        : "r"(a[0]), "r"(a[1]), "r"(a[2]), "r"(a[3]), "r"(b[0]), "r"(b[1]));
}

__device__ __forceinline__ int imin(int a, int b){ return a < b ? a : b; }
__device__ __forceinline__ uint32_t pkhf(float a, float b){
    __half2 h = __floats2half2_rn(a, b);
    return *(uint32_t*)&h;
}

__device__ __forceinline__ void mbar_init(uint32_t a, uint32_t cnt){
    asm volatile("mbarrier.init.shared.b64 [%0], %1;" :: "r"(a), "r"(cnt) : "memory");
}
__device__ __forceinline__ void mbar_wait(uint32_t a, uint32_t parity){
    uint32_t done;
    asm volatile("{.reg .pred p; mbarrier.try_wait.parity.acquire.cta.shared::cta.b64 p, [%1], %2; selp.b32 %0,1,0,p;}"
        : "=r"(done) : "r"(a), "r"(parity) : "memory");
    if (!done)
        asm volatile("{.reg .pred P1; WL%=: mbarrier.try_wait.parity.acquire.cta.shared::cta.b64 P1, [%0], %1, 0x989680;"
                     "@P1 bra.uni WD%=; bra.uni WL%=; WD%=: }" :: "r"(a), "r"(parity) : "memory");
}

// ============================================================
// prep kernels
// ============================================================
__global__ __launch_bounds__(256) void prep_vt(const float* __restrict__ normal){
    int idx = blockIdx.x*256 + threadIdx.x;      // 63*384*32 = 774144
    if (idx < NTK*384*32){
        int t = idx / (384*32);
        int rem = idx - t*(384*32);
        int n = rem >> 5, j = rem & 31;
        int kv = t*32 + j;
        float v = (kv < NN) ? normal[(size_t)kv*TD + n] : 0.f;
        g_vimg[(size_t)t*VIMG_TILE_H + n*40 + j] = __float2half_rn(v);
    }
}

__global__ __launch_bounds__(256) void prep_x(const float* __restrict__ x){
    int idx = blockIdx.x*256 + threadIdx.x;
    if (idx < (B*NN*TD)/4){
        float4 v = ((const float4*)x)[idx];
        uint2 o;
        o.x = pkhf(v.x, v.y);
        o.y = pkhf(v.z, v.w);
        ((uint2*)g_xh)[idx] = o;
    }
}

__global__ __launch_bounds__(256) void prep_wt(const float* __restrict__ Wq,
                                               const float* __restrict__ Wk){
    int idx = blockIdx.x*256 + threadIdx.x;
    if (idx < 3*128*136){
        int c = idx / (128*136);
        int rem = idx - c*(128*136);
        int n = rem / 136, kk = rem - n*136;
        float v = 0.f;
        if (kk < 128){
            int k = c*128 + kk;
            v = (n < 64) ? Wq[k*64 + n] : Wk[k*64 + (n - 64)];
        }
        g_wt[idx] = __float2half_rn(v);
    }
}

// ============================================================
// Kernel 1: y = xh @ W (fp16 HMMA), +bias, LN -> g_qf (pre-scaled) / g_kimg
// ============================================================
__device__ __forceinline__ void k1_prefx(char* sm, int tid, long base, int c, int s){
#pragma unroll
    for (int j = 0; j < 8; j++){
        int idx = tid + j*256;
        int row = idx >> 4, ch = idx & 15;
        const __half* src = g_xh + (base + row)*(size_t)TD + c*128 + ch*8;
        cpa16(cvta_s(sm + K1_OFF_X + s*K1_XTILE + row*272 + ch*16), src);
    }
    CP_COMMIT();
}

__global__ __launch_bounds__(256, 1) void k1_tc(
    const float* __restrict__ bq, const float* __restrict__ bk,
    const float* __restrict__ g0, const float* __restrict__ beta0,
    const float* __restrict__ g1, const float* __restrict__ beta1)
{
    extern __shared__ char sm[];
    const int tid = threadIdx.x;
    const int wid = tid >> 5, lane = tid & 31;
    const int gid = lane >> 2, tig = lane & 3;
    const int r0 = wid * 16;
    const long base = (long)blockIdx.x * K1M;

    float* cs = (float*)(sm + K1_OFF_C);
    if (tid < 128){
        cs[tid]       = (tid < 64) ? bq[tid] : bk[tid - 64];
        cs[128 + tid] = (tid < 64) ? g0[tid] : g1[tid - 64];
        cs[256 + tid] = (tid < 64) ? beta0[tid] : beta1[tid - 64];
    }

    k1_prefx(sm, tid, base, 0, 0);
    {
#pragma unroll
        for (int j = 0; j < 26; j++){
            int i = tid + j*256;
            if (i < 6528)
                cpa16(cvta_s(sm + K1_OFF_W + i*16), (const char*)g_wt + i*16);
        }
        CP_COMMIT();
    }
    k1_prefx(sm, tid, base, 1, 1);

    float acc[16][4];
#pragma unroll
    for (int nt = 0; nt < 16; nt++)
#pragma unroll
        for (int j = 0; j < 4; j++) acc[nt][j] = 0.f;

#pragma unroll
    for (int c = 0; c < 3; c++){
        if (c < 2) asm volatile("cp.async.wait_group 1;");
        else       asm volatile("cp.async.wait_group 0;");
        __syncthreads();
        const uint32_t* xs  = (const uint32_t*)(sm + K1_OFF_X + (c & 1)*K1_XTILE);
        const uint32_t* wsp = (const uint32_t*)(sm + K1_OFF_W + c*K1_XTILE);
#pragma unroll
        for (int ks = 0; ks < 8; ks++){
            int qa = (r0 + gid)*K1_XST + ks*8 + tig;
            int qb = qa + 8*K1_XST;
            uint32_t a[4] = { xs[qa], xs[qb], xs[qa+4], xs[qb+4] };
#pragma unroll
            for (int nt = 0; nt < 16; nt++){
                int kb = (nt*8 + gid)*K1_XST + ks*8 + tig;
                uint32_t bfr[2] = { wsp[kb], wsp[kb+4] };
                mma16816h(acc[nt], a, bfr);
            }
        }
        __syncthreads();
        if (c == 0){ k1_prefx(sm, tid, base, 2, 0); }
    }

    const int c0 = tig*2;
#pragma unroll
    for (int nt = 0; nt < 16; nt++){
        int col = (nt < 8) ? nt*8 + c0 : 64 + (nt - 8)*8 + c0;
        float b0 = cs[col], b1 = cs[col + 1];
        acc[nt][0] += b0; acc[nt][1] += b1;
        acc[nt][2] += b0; acc[nt][3] += b1;
    }
    float sqA=0,ssA=0,skA=0,sskA=0, sqB=0,ssB=0,skB=0,sskB=0;
#pragma unroll
    for (int nt = 0; nt < 8; nt++){
        sqA += acc[nt][0] + acc[nt][1];
        ssA += acc[nt][0]*acc[nt][0] + acc[nt][1]*acc[nt][1];
        sqB += acc[nt][2] + acc[nt][3];
        ssB += acc[nt][2]*acc[nt][2] + acc[nt][3]*acc[nt][3];
    }
#pragma unroll
    for (int nt = 8; nt < 16; nt++){
        skA += acc[nt][0] + acc[nt][1];
        sskA += acc[nt][0]*acc[nt][0] + acc[nt][1]*acc[nt][1];
        skB += acc[nt][2] + acc[nt][3];
        sskB += acc[nt][2]*acc[nt][2] + acc[nt][3]*acc[nt][3];
    }
#pragma unroll
    for (int off = 1; off <= 2; off <<= 1){
        sqA += __shfl_xor_sync(0xffffffffu, sqA, off);
        ssA += __shfl_xor_sync(0xffffffffu, ssA, off);
        skA += __shfl_xor_sync(0xffffffffu, skA, off);
        sskA += __shfl_xor_sync(0xffffffffu, sskA, off);
        sqB += __shfl_xor_sync(0xffffffffu, sqB, off);
        ssB += __shfl_xor_sync(0xffffffffu, ssB, off);
        skB += __shfl_xor_sync(0xffffffffu, skB, off);
        sskB += __shfl_xor_sync(0xffffffffu, sskB, off);
    }
    const float inv64 = 1.f/64.f;
    float muqA = sqA*inv64, rsqA = rsqrtf(ssA*inv64 - muqA*muqA + 1e-5f) * SCALE_S;
    float muqB = sqB*inv64, rsqB = rsqrtf(ssB*inv64 - muqB*muqB + 1e-5f) * SCALE_S;
    float mukA = skA*inv64, rskA = rsqrtf(sskA*inv64 - mukA*mukA + 1e-5f);
    float mukB = skB*inv64, rskB = rsqrtf(sskB*inv64 - mukB*mukB + 1e-5f);

    const int grA = (int)(base + r0 + gid);
    const int grB = grA + 8;
    const int bA = grA / NN, nAq = grA - bA*NN;
    const int bB = grB / NN, nBq = grB - bB*NN;
    __half* kdstA = g_kimg + (size_t)bA*KIMG_BATCH_H + (nAq >> 5)*KIMG_TILE_H + (nAq & 31)*72;
    __half* kdstB = g_kimg + (size_t)bB*KIMG_BATCH_H + (nBq >> 5)*KIMG_TILE_H + (nBq & 31)*72;

#pragma unroll
    for (int nt = 0; nt < 8; nt++){
        int col = nt*8 + c0;
        float ga = cs[128 + col], gb = cs[128 + col + 1];
        float ba = cs[256 + col] * SCALE_S, bb = cs[256 + col + 1] * SCALE_S;
        *(uint32_t*)(g_qf + (size_t)grA*E + col) =
            pkhf((acc[nt][0]-muqA)*rsqA*ga + ba, (acc[nt][1]-muqA)*rsqA*gb + bb);
        *(uint32_t*)(g_qf + (size_t)grB*E + col) =
            pkhf((acc[nt][2]-muqB)*rsqB*ga + ba, (acc[nt][3]-muqB)*rsqB*gb + bb);
    }
#pragma unroll
    for (int nt = 8; nt < 16; nt++){
        int col = (nt - 8)*8 + c0;
        float ga = cs[128 + 64 + col], gb = cs[128 + 64 + col + 1];
        float ba = cs[256 + 64 + col], bb = cs[256 + 64 + col + 1];
        *(uint32_t*)(kdstA + col) =
            pkhf((acc[nt][0]-mukA)*rskA*ga + ba, (acc[nt][1]-mukA)*rskA*gb + bb);
        *(uint32_t*)(kdstB + col) =
            pkhf((acc[nt][2]-mukB)*rskB*ga + ba, (acc[nt][3]-mukB)*rskB*gb + bb);
    }
}

// ============================================================
// Kernel 2: fp16 mma.sync flash attention.
// BR=64, 128 threads, 2 CTAs/SM; 32-kv bulk double-buffered stages;
// P in registers; __expf; scale pre-folded into q.
// ============================================================
__device__ __forceinline__ void issue_tile(char* smem, int t, int b){
    if (t < NTK){
        int st = t & 1;
        uint32_t mbar = cvta_s(smem + OFF_MB + st*8);
        uint32_t kdst = cvta_s(smem + OFF_ST + st*STG);
        uint32_t vdst = kdst + KIMG_TILE_B;
        asm volatile("mbarrier.arrive.expect_tx.shared.b64 _, [%0], %1;"
            :: "r"(mbar), "r"((uint32_t)STG) : "memory");
        const char* ksrc = (const char*)(g_kimg + (size_t)b*KIMG_BATCH_H) + (size_t)t*KIMG_TILE_B;
        const char* vsrc = (const char*)g_vimg + (size_t)t*VIMG_TILE_B;
        asm volatile("cp.async.bulk.shared::cta.global.mbarrier::complete_tx::bytes [%0], [%1], %2, [%3];"
            :: "r"(kdst), "l"(ksrc), "r"((uint32_t)KIMG_TILE_B), "r"(mbar) : "memory");
        asm volatile("cp.async.bulk.shared::cta.global.mbarrier::complete_tx::bytes [%0], [%1], %2, [%3];"
            :: "r"(vdst), "l"(vsrc), "r"((uint32_t)VIMG_TILE_B), "r"(mbar) : "memory");
    }
}

__global__ __launch_bounds__(128, 2) void attn_mma(
    const float* __restrict__ x,
    const float* __restrict__ Win,
    float* __restrict__ out)
{
    extern __shared__ char smem[];
    const int tid = threadIdx.x;
    const int wid = tid >> 5, lane = tid & 31;
    const int gid = lane >> 2, tig = lane & 3;
    const int b = blockIdx.y;
    const int n0 = blockIdx.x * BR;
    const int r0 = wid * 16;

    // Q prologue: 512 chunks
#pragma unroll
    for (int j = 0; j < 4; j++){
        int c = tid + j*128;
        int row = c >> 3, ch = c & 7;
        int g = imin(n0 + row, NN-1);
        const __half* src = g_qf + ((size_t)b*NN + g)*E + ch*8;
        cpa16(cvta_s(smem + OFF_Q + row*144 + ch*16), src);
    }
    CP_COMMIT();

    if (tid == 0){
        mbar_init(cvta_s(smem + OFF_MB), 1);
        mbar_init(cvta_s(smem + OFF_MB + 8), 1);
    }
    __syncthreads();
    if (tid == 0){
        issue_tile(smem, 0, b);
        issue_tile(smem, 1, b);
    }
    asm volatile("cp.async.wait_group 0;");
    __syncthreads();

    float dacc[48][4];
#pragma unroll
    for (int nt = 0; nt < 48; nt++)
#pragma unroll
        for (int c = 0; c < 4; c++) dacc[nt][c] = 0.f;
    float lA = 0.f, lB = 0.f;

    const uint32_t* qf_s = (const uint32_t*)(smem + OFF_Q);

    for (int t = 0; t < NTK; t++){
        const int st = t & 1;
        mbar_wait(cvta_s(smem + OFF_MB + st*8), (t >> 1) & 1);

        const uint32_t* kh = (const uint32_t*)(smem + OFF_ST + st*STG);
        const uint32_t* vh = (const uint32_t*)(smem + OFF_ST + st*STG + KIMG_TILE_B);

        // ---- S = Q.K (16 MMAs/warp); q pre-scaled
        float sacc[4][4];
#pragma unroll
        for (int nt = 0; nt < 4; nt++)
#pragma unroll
            for (int c = 0; c < 4; c++) sacc[nt][c] = 0.f;
#pragma unroll
        for (int ks = 0; ks < 4; ks++){
            int qa = (r0 + gid)*36 + ks*8 + tig;
            int qb = qa + 8*36;
            uint32_t ah[4] = { qf_s[qa], qf_s[qb], qf_s[qa+4], qf_s[qb+4] };
#pragma unroll
            for (int nt = 0; nt < 4; nt++){
                int kb = (nt*8 + gid)*36 + ks*8 + tig;
                uint32_t bh[2] = { kh[kb], kh[kb+4] };
                mma16816h(sacc[nt], ah, bh);
            }
        }

        // ---- exp (MUFU), masked
#pragma unroll
        for (int nt = 0; nt < 4; nt++){
            int colg = t*32 + nt*8 + tig*2;
            bool m0 = colg < NN, m1 = (colg + 1) < NN;
            float p0 = m0 ? __expf(sacc[nt][0]) : 0.f;
            float p1 = m1 ? __expf(sacc[nt][1]) : 0.f;
            float p2 = m0 ? __expf(sacc[nt][2]) : 0.f;
            float p3 = m1 ? __expf(sacc[nt][3]) : 0.f;
            lA += p0 + p1; lB += p2 + p3;
            sacc[nt][0] = p0; sacc[nt][1] = p1;
            sacc[nt][2] = p2; sacc[nt][3] = p3;
        }

        // ---- PV: P a-frags from sacc (96 MMAs/warp)
#pragma unroll
        for (int ks = 0; ks < 2; ks++){
            uint32_t pa[4] = {
                pkhf(sacc[2*ks][0],   sacc[2*ks][1]),
                pkhf(sacc[2*ks][2],   sacc[2*ks][3]),
                pkhf(sacc[2*ks+1][0], sacc[2*ks+1][1]),
                pkhf(sacc[2*ks+1][2], sacc[2*ks+1][3])
            };
#pragma unroll
            for (int nt = 0; nt < 48; nt++){
                int vb = (nt*8 + gid)*20 + ks*8 + tig;
                uint32_t bh[2] = { vh[vb], vh[vb+4] };
                mma16816h(dacc[nt], pa, bh);
            }
        }
        __syncthreads();                 // all warps done with stage st
        if (tid == 0) issue_tile(smem, t + 2, b);
    }

    // ---- epilogue
    lA += __shfl_xor_sync(0xffffffffu, lA, 1);
    lA += __shfl_xor_sync(0xffffffffu, lA, 2);
    lB += __shfl_xor_sync(0xffffffffu, lB, 1);
    lB += __shfl_xor_sync(0xffffffffu, lB, 2);
    const float invA = 1.f / lA;
    const float invB = 1.f / lB;

    const int nA = imin(n0 + r0 + gid, NN-1);
    const int nB = imin(n0 + r0 + gid + 8, NN-1);
    float q16A[DD], q16B[DD];
    {
        const float* xa = x + ((size_t)b*NN + nA)*TD + (TT-1)*DD;
        const float* xb = x + ((size_t)b*NN + nB)*TD + (TT-1)*DD;
#pragma unroll
        for (int dp = 0; dp < DD; dp++){
            float sa = 0.f, sb = 0.f;
#pragma unroll
            for (int d = 0; d < DD; d++){
                float w = Win[d*DD + dp];
                sa = fmaf(xa[d], w, sa);
                sb = fmaf(xb[d], w, sb);
            }
            q16A[dp] = sa; q16B[dp] = sb;
        }
    }

    float wAr[TT], wBr[TT];
#pragma unroll
    for (int t2 = 0; t2 < TT; t2++){
        int nt0 = 2*t2, nt1 = nt0 + 1;
        float aA = q16A[tig*2]   * dacc[nt0][0] + q16A[tig*2+1]   * dacc[nt0][1]
                 + q16A[8+tig*2] * dacc[nt1][0] + q16A[9+tig*2]   * dacc[nt1][1];
        float aB = q16B[tig*2]   * dacc[nt0][2] + q16B[tig*2+1]   * dacc[nt0][3]
                 + q16B[8+tig*2] * dacc[nt1][2] + q16B[9+tig*2]   * dacc[nt1][3];
        aA += __shfl_xor_sync(0xffffffffu, aA, 1);
        aA += __shfl_xor_sync(0xffffffffu, aA, 2);
        aB += __shfl_xor_sync(0xffffffffu, aB, 1);
        aB += __shfl_xor_sync(0xffffffffu, aB, 2);
        wAr[t2] = aA * invA;
        wBr[t2] = aB * invB;
    }
    {
        float mA = -1e30f, mB = -1e30f;
#pragma unroll
        for (int t2 = 0; t2 < TT; t2++){ mA = fmaxf(mA, wAr[t2]); mB = fmaxf(mB, wBr[t2]); }
        float sA = 0.f, sB = 0.f;
#pragma unroll
        for (int t2 = 0; t2 < TT; t2++){
            float eA = __expf(wAr[t2] - mA); wAr[t2] = eA; sA += eA;
            float eB = __expf(wBr[t2] - mB); wBr[t2] = eB; sB += eB;
        }
        float iA = 1.f / sA, iB = 1.f / sB;
#pragma unroll
        for (int t2 = 0; t2 < TT; t2++){ wAr[t2] *= iA; wBr[t2] *= iB; }
    }

    const bool vA = (n0 + r0 + gid) < NN;
    const bool vB = (n0 + r0 + gid + 8) < NN;
    float* orowA = out + ((size_t)b*NN + nA)*TD;
    float* orowB = out + ((size_t)b*NN + nB)*TD;
#pragma unroll
    for (int nt = 0; nt < 48; nt++){
        int col = nt*8 + tig*2;
        int t2 = nt >> 1;
        if (vA){
            float2 v; v.x = fmaf(dacc[nt][0], invA, wAr[t2]);
            v.y = fmaf(dacc[nt][1], invA, wAr[t2]);
            *(float2*)(orowA + col) = v;
        }
        if (vB){
            float2 v; v.x = fmaf(dacc[nt][2], invB, wBr[t2]);
            v.y = fmaf(dacc[nt][3], invB, wBr[t2]);
            *(float2*)(orowB + col) = v;
        }
    }
}

// ============================================================
extern "C" void kernel_launch(void* const* d_in, const int* in_sizes, int n_in,
                              void* d_out, int out_size)
{
    (void)in_sizes; (void)n_in; (void)out_size;
    const float* x     = (const float*)d_in[0];
    const float* Wq    = (const float*)d_in[1];
    const float* bq    = (const float*)d_in[2];
    const float* Wk    = (const float*)d_in[3];
    const float* bk    = (const float*)d_in[4];
    const float* g0    = (const float*)d_in[5];
    const float* beta0 = (const float*)d_in[6];
    const float* g1    = (const float*)d_in[7];
    const float* beta1 = (const float*)d_in[8];
    const float* nrm   = (const float*)d_in[9];
    const float* Win   = (const float*)d_in[10];
    float* out = (float*)d_out;

    cudaFuncSetAttribute(k1_tc,    cudaFuncAttributeMaxDynamicSharedMemorySize, K1_SMEM);
    cudaFuncSetAttribute(attn_mma, cudaFuncAttributeMaxDynamicSharedMemorySize, SMEM_ATT);

    prep_vt<<<(NTK*384*32 + 255)/256, 256>>>(nrm);
    prep_x<<<((B*NN*TD)/4 + 255)/256, 256>>>(x);
    prep_wt<<<(3*128*136 + 255)/256, 256>>>(Wq, Wk);

    k1_tc<<<(B*NN)/K1M, 256, K1_SMEM>>>(bq, bk, g0, beta0, g1, beta1);

    dim3 grid((NN + BR - 1)/BR, B);
    attn_mma<<<grid, 128, SMEM_ATT>>>(x, Win, out);
}

// round 17
// speedup vs baseline: 1.1507x; 1.0234x over previous
#include <cuda_runtime.h>
#include <cuda_fp16.h>
#include <cstdint>

#define B    32
#define NN   2000
#define TD   384
#define E    64
#define TT   24
#define DD   16

#define BR   64
#define NTK  63                          // 63 tiles x 32 kv

// ---- K/V gmem tile-image geometry (exact smem images)
#define KIMG_TILE_H   2304               // 32 rows x 72 halves
#define KIMG_TILE_B   4608
#define KIMG_BATCH_H  145152             // 63 tiles
#define VIMG_TILE_H   15360              // 384 rows x 40 halves
#define VIMG_TILE_B   30720

// ---- attn smem byte layout
#define OFF_Q   0                        // 64 rows x 144B = 9216
#define OFF_MB  9216                     // 2 mbarriers
#define OFF_ST  9728                     // 2 stages x (K 4608 + V 30720)
#define STG     35328
#define SMEM_ATT (OFF_ST + 2*STG)        // 80384

// ---- k1 tensor-GEMM layout (64 rows/CTA, 128 thr, 2 CTAs/SM)
#define K1M     64
#define K1_XST  68                       // uints per 272B row
#define K1_XT_B 17408                    // 64 rows x 272B
#define K1_WT_B 34816                    // 128 n-rows x 272B
#define K1_OFF_X 0                       // 2 stages x 17408
#define K1_OFF_W 34816                   // 2 stages x 34816
#define K1_OFF_C 104448                  // 384 floats
#define K1_SMEM  105984

#define SCALE_S 0.022360679774997897f    // 1/sqrt(2000)

// fused prep index spaces
#define PX  ((B*NN*TD)/4)                // 1,536,000 float4s
#define PV  (NTK*384*32)                 // 774,144
#define PW  (3*128*136)                  // 52,224

typedef unsigned long long u64;

__device__ __align__(16) __half g_qf[B*NN*E];        // pre-scaled by SCALE_S
__device__ __align__(16) __half g_kimg[B*KIMG_BATCH_H];
__device__ __align__(16) __half g_vimg[NTK*VIMG_TILE_H];
__device__ __align__(16) __half g_xh[B*NN*TD];
__device__ __align__(16) __half g_wt[3*128*136];

// =================== helpers ===================
__device__ __forceinline__ uint32_t cvta_s(const void* p){
    return (uint32_t)__cvta_generic_to_shared(p);
}
__device__ __forceinline__ void cpa16(uint32_t d, const void* s){
    asm volatile("cp.async.cg.shared.global [%0],[%1],16;" :: "r"(d), "l"(s));
}
#define CP_COMMIT() asm volatile("cp.async.commit_group;")

__device__ __forceinline__ void mma16816h(float* d, const uint32_t* a, const uint32_t* b){
    asm volatile("mma.sync.aligned.m16n8k16.row.col.f32.f16.f16.f32 "
        "{%0,%1,%2,%3},{%4,%5,%6,%7},{%8,%9},{%0,%1,%2,%3};"
        : "+f"(d[0]), "+f"(d[1]), "+f"(d[2]), "+f"(d[3])
        : "r"(a[0]), "r"(a[1]), "r"(a[2]), "r"(a[3]), "r"(b[0]), "r"(b[1]));
}

__device__ __forceinline__ int imin(int a, int b){ return a < b ? a : b; }
__device__ __forceinline__ uint32_t pkhf(float a, float b){
    __half2 h = __floats2half2_rn(a, b);
    return *(uint32_t*)&h;
}

__device__ __forceinline__ void mbar_init(uint32_t a, uint32_t cnt){
    asm volatile("mbarrier.init.shared.b64 [%0], %1;" :: "r"(a), "r"(cnt) : "memory");
}
__device__ __forceinline__ void mbar_wait(uint32_t a, uint32_t parity){
    uint32_t done;
    asm volatile("{.reg .pred p; mbarrier.try_wait.parity.acquire.cta.shared::cta.b64 p, [%1], %2; selp.b32 %0,1,0,p;}"
        : "=r"(done) : "r"(a), "r"(parity) : "memory");
    if (!done)
        asm volatile("{.reg .pred P1; WL%=: mbarrier.try_wait.parity.acquire.cta.shared::cta.b64 P1, [%0], %1, 0x989680;"
                     "@P1 bra.uni WD%=; bra.uni WL%=; WD%=: }" :: "r"(a), "r"(parity) : "memory");
}

// ============================================================
// fused prep: x -> fp16, V tile images, W transpose/pad
// ============================================================
__global__ __launch_bounds__(256) void prep_all(
    const float* __restrict__ x,
    const float* __restrict__ normal,
    const float* __restrict__ Wq,
    const float* __restrict__ Wk)
{
    int idx = blockIdx.x*256 + threadIdx.x;
    if (idx < PX){
        float4 v = ((const float4*)x)[idx];
        uint2 o;
        o.x = pkhf(v.x, v.y);
        o.y = pkhf(v.z, v.w);
        ((uint2*)g_xh)[idx] = o;
    } else if (idx < PX + PV){
        int i = idx - PX;
        int t = i / (384*32);
        int rem = i - t*(384*32);
        int n = rem >> 5, j = rem & 31;
        int kv = t*32 + j;
        float v = (kv < NN) ? normal[(size_t)kv*TD + n] : 0.f;
        g_vimg[(size_t)t*VIMG_TILE_H + n*40 + j] = __float2half_rn(v);
    } else if (idx < PX + PV + PW){
        int i = idx - PX - PV;
        int c = i / (128*136);
        int rem = i - c*(128*136);
        int n = rem / 136, kk = rem - n*136;
        float v = 0.f;
        if (kk < 128){
            int k = c*128 + kk;
            v = (n < 64) ? Wq[k*64 + n] : Wk[k*64 + (n - 64)];
        }
        g_wt[i] = __float2half_rn(v);
    }
}

// ============================================================
// Kernel 1: y = xh @ W (fp16 HMMA), +bias, LN -> g_qf (pre-scaled) / g_kimg
// 64 rows/CTA, 128 threads (4 warps x 16 rows), 2 CTAs/SM.
// X and W chunks both double-buffered.
// ============================================================
__device__ __forceinline__ void k1_pref(char* sm, int tid, long base, int c, int s){
    if (c < 3){
        // X chunk: 1024 x 16B
#pragma unroll
        for (int j = 0; j < 8; j++){
            int idx = tid + j*128;
            int row = idx >> 4, ch = idx & 15;
            const __half* src = g_xh + (base + row)*(size_t)TD + c*128 + ch*8;
            cpa16(cvta_s(sm + K1_OFF_X + s*K1_XT_B + row*272 + ch*16), src);
        }
        // W chunk: 2176 x 16B
#pragma unroll
        for (int j = 0; j < 17; j++){
            int i = tid + j*128;
            cpa16(cvta_s(sm + K1_OFF_W + s*K1_WT_B + i*16),
                  (const char*)g_wt + (size_t)c*K1_WT_B + i*16);
        }
    }
    CP_COMMIT();
}

__global__ __launch_bounds__(128, 2) void k1_tc(
    const float* __restrict__ bq, const float* __restrict__ bk,
    const float* __restrict__ g0, const float* __restrict__ beta0,
    const float* __restrict__ g1, const float* __restrict__ beta1)
{
    extern __shared__ char sm[];
    const int tid = threadIdx.x;
    const int wid = tid >> 5, lane = tid & 31;
    const int gid = lane >> 2, tig = lane & 3;
    const int r0 = wid * 16;
    const long base = (long)blockIdx.x * K1M;

    float* cs = (float*)(sm + K1_OFF_C);
    cs[tid]       = (tid < 64) ? bq[tid] : bk[tid - 64];
    cs[128 + tid] = (tid < 64) ? g0[tid] : g1[tid - 64];
    cs[256 + tid] = (tid < 64) ? beta0[tid] : beta1[tid - 64];

    k1_pref(sm, tid, base, 0, 0);
    k1_pref(sm, tid, base, 1, 1);

    float acc[16][4];
#pragma unroll
    for (int nt = 0; nt < 16; nt++)
#pragma unroll
        for (int j = 0; j < 4; j++) acc[nt][j] = 0.f;

#pragma unroll
    for (int c = 0; c < 3; c++){
        if (c < 2) asm volatile("cp.async.wait_group 1;");
        else       asm volatile("cp.async.wait_group 0;");
        __syncthreads();
        const uint32_t* xs  = (const uint32_t*)(sm + K1_OFF_X + (c & 1)*K1_XT_B);
        const uint32_t* wsp = (const uint32_t*)(sm + K1_OFF_W + (c & 1)*K1_WT_B);
#pragma unroll
        for (int ks = 0; ks < 8; ks++){
            int qa = (r0 + gid)*K1_XST + ks*8 + tig;
            int qb = qa + 8*K1_XST;
            uint32_t a[4] = { xs[qa], xs[qb], xs[qa+4], xs[qb+4] };
#pragma unroll
            for (int nt = 0; nt < 16; nt++){
                int kb = (nt*8 + gid)*K1_XST + ks*8 + tig;
                uint32_t bfr[2] = { wsp[kb], wsp[kb+4] };
                mma16816h(acc[nt], a, bfr);
            }
        }
        __syncthreads();
        if (c == 0){ k1_pref(sm, tid, base, 2, 0); }
    }

    const int c0 = tig*2;
#pragma unroll
    for (int nt = 0; nt < 16; nt++){
        int col = (nt < 8) ? nt*8 + c0 : 64 + (nt - 8)*8 + c0;
        float b0 = cs[col], b1 = cs[col + 1];
        acc[nt][0] += b0; acc[nt][1] += b1;
        acc[nt][2] += b0; acc[nt][3] += b1;
    }
    float sqA=0,ssA=0,skA=0,sskA=0, sqB=0,ssB=0,skB=0,sskB=0;
#pragma unroll
    for (int nt = 0; nt < 8; nt++){
        sqA += acc[nt][0] + acc[nt][1];
        ssA += acc[nt][0]*acc[nt][0] + acc[nt][1]*acc[nt][1];
        sqB += acc[nt][2] + acc[nt][3];
        ssB += acc[nt][2]*acc[nt][2] + acc[nt][3]*acc[nt][3];
    }
#pragma unroll
    for (int nt = 8; nt < 16; nt++){
        skA += acc[nt][0] + acc[nt][1];
        sskA += acc[nt][0]*acc[nt][0] + acc[nt][1]*acc[nt][1];
        skB += acc[nt][2] + acc[nt][3];
        sskB += acc[nt][2]*acc[nt][2] + acc[nt][3]*acc[nt][3];
    }
#pragma unroll
    for (int off = 1; off <= 2; off <<= 1){
        sqA += __shfl_xor_sync(0xffffffffu, sqA, off);
        ssA += __shfl_xor_sync(0xffffffffu, ssA, off);
        skA += __shfl_xor_sync(0xffffffffu, skA, off);
        sskA += __shfl_xor_sync(0xffffffffu, sskA, off);
        sqB += __shfl_xor_sync(0xffffffffu, sqB, off);
        ssB += __shfl_xor_sync(0xffffffffu, ssB, off);
        skB += __shfl_xor_sync(0xffffffffu, skB, off);
        sskB += __shfl_xor_sync(0xffffffffu, sskB, off);
    }
    const float inv64 = 1.f/64.f;
    float muqA = sqA*inv64, rsqA = rsqrtf(ssA*inv64 - muqA*muqA + 1e-5f) * SCALE_S;
    float muqB = sqB*inv64, rsqB = rsqrtf(ssB*inv64 - muqB*muqB + 1e-5f) * SCALE_S;
    float mukA = skA*inv64, rskA = rsqrtf(sskA*inv64 - mukA*mukA + 1e-5f);
    float mukB = skB*inv64, rskB = rsqrtf(sskB*inv64 - mukB*mukB + 1e-5f);

    const int grA = (int)(base + r0 + gid);
    const int grB = grA + 8;
    const int bA = grA / NN, nAq = grA - bA*NN;
    const int bB = grB / NN, nBq = grB - bB*NN;
    __half* kdstA = g_kimg + (size_t)bA*KIMG_BATCH_H + (nAq >> 5)*KIMG_TILE_H + (nAq & 31)*72;
    __half* kdstB = g_kimg + (size_t)bB*KIMG_BATCH_H + (nBq >> 5)*KIMG_TILE_H + (nBq & 31)*72;

#pragma unroll
    for (int nt = 0; nt < 8; nt++){
        int col = nt*8 + c0;
        float ga = cs[128 + col], gb = cs[128 + col + 1];
        float ba = cs[256 + col] * SCALE_S, bb = cs[256 + col + 1] * SCALE_S;
        *(uint32_t*)(g_qf + (size_t)grA*E + col) =
            pkhf((acc[nt][0]-muqA)*rsqA*ga + ba, (acc[nt][1]-muqA)*rsqA*gb + bb);
        *(uint32_t*)(g_qf + (size_t)grB*E + col) =
            pkhf((acc[nt][2]-muqB)*rsqB*ga + ba, (acc[nt][3]-muqB)*rsqB*gb + bb);
    }
#pragma unroll
    for (int nt = 8; nt < 16; nt++){
        int col = (nt - 8)*8 + c0;
        float ga = cs[128 + 64 + col], gb = cs[128 + 64 + col + 1];
        float ba = cs[256 + 64 + col], bb = cs[256 + 64 + col + 1];
        *(uint32_t*)(kdstA + col) =
            pkhf((acc[nt][0]-mukA)*rskA*ga + ba, (acc[nt][1]-mukA)*rskA*gb + bb);
        *(uint32_t*)(kdstB + col) =
            pkhf((acc[nt][2]-mukB)*rskB*ga + ba, (acc[nt][3]-mukB)*rskB*gb + bb);
    }
}

// ============================================================
// Kernel 2: fp16 mma.sync flash attention (unchanged from R16 —
// at the legacy-HMMA roofline). BR=64, 128 thr, 2 CTAs/SM,
// 32-kv bulk double-buffered stages, P in registers, __expf.
// ============================================================
__device__ __forceinline__ void issue_tile(char* smem, int t, int b){
    if (t < NTK){
        int st = t & 1;
        uint32_t mbar = cvta_s(smem + OFF_MB + st*8);
        uint32_t kdst = cvta_s(smem + OFF_ST + st*STG);
        uint32_t vdst = kdst + KIMG_TILE_B;
        asm volatile("mbarrier.arrive.expect_tx.shared.b64 _, [%0], %1;"
            :: "r"(mbar), "r"((uint32_t)STG) : "memory");
        const char* ksrc = (const char*)(g_kimg + (size_t)b*KIMG_BATCH_H) + (size_t)t*KIMG_TILE_B;
        const char* vsrc = (const char*)g_vimg + (size_t)t*VIMG_TILE_B;
        asm volatile("cp.async.bulk.shared::cta.global.mbarrier::complete_tx::bytes [%0], [%1], %2, [%3];"
            :: "r"(kdst), "l"(ksrc), "r"((uint32_t)KIMG_TILE_B), "r"(mbar) : "memory");
        asm volatile("cp.async.bulk.shared::cta.global.mbarrier::complete_tx::bytes [%0], [%1], %2, [%3];"
            :: "r"(vdst), "l"(vsrc), "r"((uint32_t)VIMG_TILE_B), "r"(mbar) : "memory");
    }
}

__global__ __launch_bounds__(128, 2) void attn_mma(
    const float* __restrict__ x,
    const float* __restrict__ Win,
    float* __restrict__ out)
{
    extern __shared__ char smem[];
    const int tid = threadIdx.x;
    const int wid = tid >> 5, lane = tid & 31;
    const int gid = lane >> 2, tig = lane & 3;
    const int b = blockIdx.y;
    const int n0 = blockIdx.x * BR;
    const int r0 = wid * 16;

    // Q prologue: 512 chunks
#pragma unroll
    for (int j = 0; j < 4; j++){
        int c = tid + j*128;
        int row = c >> 3, ch = c & 7;
        int g = imin(n0 + row, NN-1);
        const __half* src = g_qf + ((size_t)b*NN + g)*E + ch*8;
        cpa16(cvta_s(smem + OFF_Q + row*144 + ch*16), src);
    }
    CP_COMMIT();

    if (tid == 0){
        mbar_init(cvta_s(smem + OFF_MB), 1);
        mbar_init(cvta_s(smem + OFF_MB + 8), 1);
    }
    __syncthreads();
    if (tid == 0){
        issue_tile(smem, 0, b);
        issue_tile(smem, 1, b);
    }
    asm volatile("cp.async.wait_group 0;");
    __syncthreads();

    float dacc[48][4];
#pragma unroll
    for (int nt = 0; nt < 48; nt++)
#pragma unroll
        for (int c = 0; c < 4; c++) dacc[nt][c] = 0.f;
    float lA = 0.f, lB = 0.f;

    const uint32_t* qf_s = (const uint32_t*)(smem + OFF_Q);

    for (int t = 0; t < NTK; t++){
        const int st = t & 1;
        mbar_wait(cvta_s(smem + OFF_MB + st*8), (t >> 1) & 1);

        const uint32_t* kh = (const uint32_t*)(smem + OFF_ST + st*STG);
        const uint32_t* vh = (const uint32_t*)(smem + OFF_ST + st*STG + KIMG_TILE_B);

        // ---- S = Q.K (16 MMAs/warp); q pre-scaled
        float sacc[4][4];
#pragma unroll
        for (int nt = 0; nt < 4; nt++)
#pragma unroll
            for (int c = 0; c < 4; c++) sacc[nt][c] = 0.f;
#pragma unroll
        for (int ks = 0; ks < 4; ks++){
            int qa = (r0 + gid)*36 + ks*8 + tig;
            int qb = qa + 8*36;
            uint32_t ah[4] = { qf_s[qa], qf_s[qb], qf_s[qa+4], qf_s[qb+4] };
#pragma unroll
            for (int nt = 0; nt < 4; nt++){
                int kb = (nt*8 + gid)*36 + ks*8 + tig;
                uint32_t bh[2] = { kh[kb], kh[kb+4] };
                mma16816h(sacc[nt], ah, bh);
            }
        }

        // ---- exp (MUFU), masked
#pragma unroll
        for (int nt = 0; nt < 4; nt++){
            int colg = t*32 + nt*8 + tig*2;
            bool m0 = colg < NN, m1 = (colg + 1) < NN;
            float p0 = m0 ? __expf(sacc[nt][0]) : 0.f;
            float p1 = m1 ? __expf(sacc[nt][1]) : 0.f;
            float p2 = m0 ? __expf(sacc[nt][2]) : 0.f;
            float p3 = m1 ? __expf(sacc[nt][3]) : 0.f;
            lA += p0 + p1; lB += p2 + p3;
            sacc[nt][0] = p0; sacc[nt][1] = p1;
            sacc[nt][2] = p2; sacc[nt][3] = p3;
        }

        // ---- PV: P a-frags from sacc (96 MMAs/warp)
#pragma unroll
        for (int ks = 0; ks < 2; ks++){
            uint32_t pa[4] = {
                pkhf(sacc[2*ks][0],   sacc[2*ks][1]),
                pkhf(sacc[2*ks][2],   sacc[2*ks][3]),
                pkhf(sacc[2*ks+1][0], sacc[2*ks+1][1]),
                pkhf(sacc[2*ks+1][2], sacc[2*ks+1][3])
            };
#pragma unroll
            for (int nt = 0; nt < 48; nt++){
                int vb = (nt*8 + gid)*20 + ks*8 + tig;
                uint32_t bh[2] = { vh[vb], vh[vb+4] };
                mma16816h(dacc[nt], pa, bh);
            }
        }
        __syncthreads();                 // all warps done with stage st
        if (tid == 0) issue_tile(smem, t + 2, b);
    }

    // ---- epilogue
    lA += __shfl_xor_sync(0xffffffffu, lA, 1);
    lA += __shfl_xor_sync(0xffffffffu, lA, 2);
    lB += __shfl_xor_sync(0xffffffffu, lB, 1);
    lB += __shfl_xor_sync(0xffffffffu, lB, 2);
    const float invA = 1.f / lA;
    const float invB = 1.f / lB;

    const int nA = imin(n0 + r0 + gid, NN-1);
    const int nB = imin(n0 + r0 + gid + 8, NN-1);
    float q16A[DD], q16B[DD];
    {
        const float* xa = x + ((size_t)b*NN + nA)*TD + (TT-1)*DD;
        const float* xb = x + ((size_t)b*NN + nB)*TD + (TT-1)*DD;
#pragma unroll
        for (int dp = 0; dp < DD; dp++){
            float sa = 0.f, sb = 0.f;
#pragma unroll
            for (int d = 0; d < DD; d++){
                float w = Win[d*DD + dp];
                sa = fmaf(xa[d], w, sa);
                sb = fmaf(xb[d], w, sb);
            }
            q16A[dp] = sa; q16B[dp] = sb;
        }
    }

    float wAr[TT], wBr[TT];
#pragma unroll
    for (int t2 = 0; t2 < TT; t2++){
        int nt0 = 2*t2, nt1 = nt0 + 1;
        float aA = q16A[tig*2]   * dacc[nt0][0] + q16A[tig*2+1]   * dacc[nt0][1]
                 + q16A[8+tig*2] * dacc[nt1][0] + q16A[9+tig*2]   * dacc[nt1][1];
        float aB = q16B[tig*2]   * dacc[nt0][2] + q16B[tig*2+1]   * dacc[nt0][3]
                 + q16B[8+tig*2] * dacc[nt1][2] + q16B[9+tig*2]   * dacc[nt1][3];
        aA += __shfl_xor_sync(0xffffffffu, aA, 1);
        aA += __shfl_xor_sync(0xffffffffu, aA, 2);
        aB += __shfl_xor_sync(0xffffffffu, aB, 1);
        aB += __shfl_xor_sync(0xffffffffu, aB, 2);
        wAr[t2] = aA * invA;
        wBr[t2] = aB * invB;
    }
    {
        float mA = -1e30f, mB = -1e30f;
#pragma unroll
        for (int t2 = 0; t2 < TT; t2++){ mA = fmaxf(mA, wAr[t2]); mB = fmaxf(mB, wBr[t2]); }
        float sA = 0.f, sB = 0.f;
#pragma unroll
        for (int t2 = 0; t2 < TT; t2++){
            float eA = __expf(wAr[t2] - mA); wAr[t2] = eA; sA += eA;
            float eB = __expf(wBr[t2] - mB); wBr[t2] = eB; sB += eB;
        }
        float iA = 1.f / sA, iB = 1.f / sB;
#pragma unroll
        for (int t2 = 0; t2 < TT; t2++){ wAr[t2] *= iA; wBr[t2] *= iB; }
    }

    const bool vA = (n0 + r0 + gid) < NN;
    const bool vB = (n0 + r0 + gid + 8) < NN;
    float* orowA = out + ((size_t)b*NN + nA)*TD;
    float* orowB = out + ((size_t)b*NN + nB)*TD;
#pragma unroll
    for (int nt = 0; nt < 48; nt++){
        int col = nt*8 + tig*2;
        int t2 = nt >> 1;
        if (vA){
            float2 v; v.x = fmaf(dacc[nt][0], invA, wAr[t2]);
            v.y = fmaf(dacc[nt][1], invA, wAr[t2]);
            *(float2*)(orowA + col) = v;
        }
        if (vB){
            float2 v; v.x = fmaf(dacc[nt][2], invB, wBr[t2]);
            v.y = fmaf(dacc[nt][3], invB, wBr[t2]);
            *(float2*)(orowB + col) = v;
        }
    }
}

// ============================================================
extern "C" void kernel_launch(void* const* d_in, const int* in_sizes, int n_in,
                              void* d_out, int out_size)
{
    (void)in_sizes; (void)n_in; (void)out_size;
    const float* x     = (const float*)d_in[0];
    const float* Wq    = (const float*)d_in[1];
    const float* bq    = (const float*)d_in[2];
    const float* Wk    = (const float*)d_in[3];
    const float* bk    = (const float*)d_in[4];
    const float* g0    = (const float*)d_in[5];
    const float* beta0 = (const float*)d_in[6];
    const float* g1    = (const float*)d_in[7];
    const float* beta1 = (const float*)d_in[8];
    const float* nrm   = (const float*)d_in[9];
    const float* Win   = (const float*)d_in[10];
    float* out = (float*)d_out;

    cudaFuncSetAttribute(k1_tc,    cudaFuncAttributeMaxDynamicSharedMemorySize, K1_SMEM);
    cudaFuncSetAttribute(attn_mma, cudaFuncAttributeMaxDynamicSharedMemorySize, SMEM_ATT);

    prep_all<<<(PX + PV + PW + 255)/256, 256>>>(x, nrm, Wq, Wk);

    k1_tc<<<(B*NN)/K1M, 128, K1_SMEM>>>(bq, bk, g0, beta0, g1, beta1);

    dim3 grid((NN + BR - 1)/BR, B);
    attn_mma<<<grid, 128, SMEM_ATT>>>(x, Win, out);
}